// round 1
// baseline (speedup 1.0000x reference)
#include <cuda_runtime.h>
#include <cuda_bf16.h>
#include <math.h>

// ---------------------------------------------------------------------------
// Problem dims (compile-time constants)
//   C=16 columns, DCOL=256, DMEM=128, DPCM=64, EXP=4, BS=4, N=1024
//   T = BS*N = 4096 tokens, R = T*C = 65536 token-columns
// Layouts: all activations are [T, C, D] row-major => row r = t*16 + c,
//          row base = r * D. Weights: [C, Din, Dout] contiguous per column.
// ---------------------------------------------------------------------------

#define TOK   4096
#define COLS  16
#define ROWS  (TOK * COLS)      // 65536

// Output region offsets (floats), in reference tuple order
#define OFF_XOUT   0UL
#define OFF_Z      16777216UL
#define OFF_ZHAT   20971520UL
#define OFF_SURP   25165824UL
#define OFF_KC     25231360UL
#define OFF_VC     33619968UL
#define OFF_GATE   42008576UL
#define OFF_QN     42074112UL
#define OFF_VN     50462720UL
#define OFF_WN     58851328UL

// Static device scratch (allocation-free requirement)
__device__ float g_delta[(size_t)ROWS * 64];    //  16 MB
__device__ float g_gain [(size_t)ROWS * 256];   //  64 MB
__device__ float g_h    [(size_t)ROWS * 256];   //  64 MB
__device__ float g_u    [(size_t)ROWS * 1024];  // 256 MB

// ---------------------------------------------------------------------------
// Generic tiled fp32 GEMM:  Out[t,c,n] = epilogue( sum_k A[t,c,k]*W[c,k,n] + bias[c,n] )
// Block tile 64x64, K-tile 16, 256 threads, 4x4 register tile per thread.
// EPI: 0 = write Out=v and auxo = v - aux (enc: z + delta)
//      1 = plain (v)
//      2 = gain:  1 + 0.1*tanh(v)
//      3 = gelu exact: v * normcdf(v)
//      4 = residual: v + aux
// ---------------------------------------------------------------------------
template <int EPI>
__global__ __launch_bounds__(256)
void gemm_k(const float* __restrict__ A, const float* __restrict__ W,
            const float* __restrict__ bias, float* __restrict__ Out,
            const float* __restrict__ aux, float* __restrict__ auxo,
            int K, int N)
{
    const int c  = blockIdx.z;
    const int m0 = blockIdx.x * 64;
    const int n0 = blockIdx.y * 64;

    __shared__ float As[16][65];   // [k][m], padded
    __shared__ float Bs[16][64];   // [k][n]

    const int tid = threadIdx.x;
    const int ar = tid >> 2, ak = (tid & 3) * 4;   // A loader: row, k-base
    const int br = tid >> 4, bn = (tid & 15) * 4;  // B loader: k-row, n-base
    const int ty = tid >> 4, tx = tid & 15;        // compute thread coords

    const float* Aptr = A + ((size_t)(m0 + ar) * COLS + c) * K + ak;
    const float* Wptr = W + ((size_t)c * K + br) * N + n0 + bn;

    float acc[4][4];
#pragma unroll
    for (int i = 0; i < 4; i++)
#pragma unroll
        for (int j = 0; j < 4; j++) acc[i][j] = 0.f;

    for (int kt = 0; kt < K; kt += 16) {
        float4 av = *(const float4*)(Aptr + kt);
        float4 bv = *(const float4*)(Wptr + (size_t)kt * N);
        As[ak + 0][ar] = av.x;
        As[ak + 1][ar] = av.y;
        As[ak + 2][ar] = av.z;
        As[ak + 3][ar] = av.w;
        *(float4*)&Bs[br][bn] = bv;
        __syncthreads();

#pragma unroll
        for (int kk = 0; kk < 16; kk++) {
            float a0 = As[kk][ty * 4 + 0];
            float a1 = As[kk][ty * 4 + 1];
            float a2 = As[kk][ty * 4 + 2];
            float a3 = As[kk][ty * 4 + 3];
            float b0 = Bs[kk][tx * 4 + 0];
            float b1 = Bs[kk][tx * 4 + 1];
            float b2 = Bs[kk][tx * 4 + 2];
            float b3 = Bs[kk][tx * 4 + 3];
            acc[0][0] += a0 * b0; acc[0][1] += a0 * b1; acc[0][2] += a0 * b2; acc[0][3] += a0 * b3;
            acc[1][0] += a1 * b0; acc[1][1] += a1 * b1; acc[1][2] += a1 * b2; acc[1][3] += a1 * b3;
            acc[2][0] += a2 * b0; acc[2][1] += a2 * b1; acc[2][2] += a2 * b2; acc[2][3] += a2 * b3;
            acc[3][0] += a3 * b0; acc[3][1] += a3 * b1; acc[3][2] += a3 * b2; acc[3][3] += a3 * b3;
        }
        __syncthreads();
    }

#pragma unroll
    for (int i = 0; i < 4; i++) {
        const int t = m0 + ty * 4 + i;
        const size_t row = (size_t)t * COLS + c;
#pragma unroll
        for (int j = 0; j < 4; j++) {
            const int n = n0 + tx * 4 + j;
            const size_t idx = row * (size_t)N + n;
            float v = acc[i][j] + bias[c * N + n];
            if (EPI == 0) {
                Out[idx]  = v;
                auxo[idx] = v - aux[idx];
            } else if (EPI == 1) {
                Out[idx] = v;
            } else if (EPI == 2) {
                Out[idx] = 1.0f + 0.1f * tanhf(v);
            } else if (EPI == 3) {
                Out[idx] = v * normcdff(v);
            } else {  // EPI == 4
                Out[idx] = v + aux[idx];
            }
        }
    }
}

// ---------------------------------------------------------------------------
// surprise = mean(delta^2, dim=-1) over 64; gate = clip(surprise, 0, 1)
// One warp per row. Grid: 8192 blocks x 256 threads (8 warps).
// ---------------------------------------------------------------------------
__global__ __launch_bounds__(256)
void surprise_k(const float* __restrict__ delta,
                float* __restrict__ surp, float* __restrict__ gate)
{
    const int r = blockIdx.x * 8 + (threadIdx.x >> 5);
    const int lane = threadIdx.x & 31;
    const size_t base = (size_t)r * 64;
    float d0 = delta[base + lane];
    float d1 = delta[base + lane + 32];
    float s = d0 * d0 + d1 * d1;
#pragma unroll
    for (int o = 16; o > 0; o >>= 1) s += __shfl_xor_sync(0xFFFFFFFFu, s, o);
    if (lane == 0) {
        s *= (1.0f / 64.0f);
        surp[r] = s;
        gate[r] = fminf(s, 1.0f);
    }
}

// ---------------------------------------------------------------------------
// h = LayerNorm(x; ln_w, ln_b) * gain.  One warp per row of 256.
// ---------------------------------------------------------------------------
__global__ __launch_bounds__(256)
void lngain_k(const float* __restrict__ x, const float* __restrict__ ln_w,
              const float* __restrict__ ln_b, const float* __restrict__ gain,
              float* __restrict__ h)
{
    const int r = blockIdx.x * 8 + (threadIdx.x >> 5);
    const int lane = threadIdx.x & 31;
    const int c = r & (COLS - 1);
    const size_t base = (size_t)r * 256;

    float v[8];
    float sum = 0.f, sq = 0.f;
#pragma unroll
    for (int i = 0; i < 8; i++) {
        v[i] = x[base + lane + 32 * i];
        sum += v[i];
        sq  += v[i] * v[i];
    }
#pragma unroll
    for (int o = 16; o > 0; o >>= 1) {
        sum += __shfl_xor_sync(0xFFFFFFFFu, sum, o);
        sq  += __shfl_xor_sync(0xFFFFFFFFu, sq, o);
    }
    const float m  = sum * (1.0f / 256.0f);
    const float var = sq * (1.0f / 256.0f) - m * m;
    const float rs = rsqrtf(var + 1e-5f);
#pragma unroll
    for (int i = 0; i < 8; i++) {
        const int d = lane + 32 * i;
        float hv = ((v[i] - m) * rs) * ln_w[c * 256 + d] + ln_b[c * 256 + d];
        h[base + d] = hv * gain[base + d];
    }
}

// ---------------------------------------------------------------------------
// L2-normalize rows of 128 in-place. blockIdx.y selects region (k_cand / q_nov).
// ---------------------------------------------------------------------------
__global__ __launch_bounds__(256)
void unitnorm_k(float* __restrict__ p0, float* __restrict__ p1)
{
    float* p = (blockIdx.y == 0) ? p0 : p1;
    const int r = blockIdx.x * 8 + (threadIdx.x >> 5);
    const int lane = threadIdx.x & 31;
    const size_t base = (size_t)r * 128;
    float v[4];
    float s = 0.f;
#pragma unroll
    for (int i = 0; i < 4; i++) {
        v[i] = p[base + lane + 32 * i];
        s += v[i] * v[i];
    }
#pragma unroll
    for (int o = 16; o > 0; o >>= 1) s += __shfl_xor_sync(0xFFFFFFFFu, s, o);
    const float inv = 1.0f / fmaxf(sqrtf(s), 1e-12f);
#pragma unroll
    for (int i = 0; i < 4; i++) p[base + lane + 32 * i] = v[i] * inv;
}

// ---------------------------------------------------------------------------
// w_nov = sigmoid( x_out . nov_w[c] + nov_b[c] ).  One warp per row of 256.
// ---------------------------------------------------------------------------
__global__ __launch_bounds__(256)
void nov_k(const float* __restrict__ xout, const float* __restrict__ nov_w,
           const float* __restrict__ nov_b, float* __restrict__ wn)
{
    const int r = blockIdx.x * 8 + (threadIdx.x >> 5);
    const int lane = threadIdx.x & 31;
    const int c = r & (COLS - 1);
    const size_t base = (size_t)r * 256;
    float acc = 0.f;
#pragma unroll
    for (int i = 0; i < 8; i++) {
        const int d = lane + 32 * i;
        acc += xout[base + d] * nov_w[c * 256 + d];
    }
#pragma unroll
    for (int o = 16; o > 0; o >>= 1) acc += __shfl_xor_sync(0xFFFFFFFFu, acc, o);
    if (lane == 0) {
        const float z = acc + nov_b[c];
        wn[r] = 1.0f / (1.0f + expf(-z));
    }
}

// ---------------------------------------------------------------------------
// Launcher
// ---------------------------------------------------------------------------
extern "C" void kernel_launch(void* const* d_in, const int* in_sizes, int n_in,
                              void* d_out, int out_size)
{
    const float* x      = (const float*)d_in[0];
    const float* zhp    = (const float*)d_in[1];
    const float* ln_w   = (const float*)d_in[2];
    const float* ln_b   = (const float*)d_in[3];
    const float* up_w   = (const float*)d_in[4];
    const float* up_b   = (const float*)d_in[5];
    const float* down_w = (const float*)d_in[6];
    const float* down_b = (const float*)d_in[7];
    const float* enc_w  = (const float*)d_in[8];
    const float* enc_b  = (const float*)d_in[9];
    const float* pred_w = (const float*)d_in[10];
    const float* pred_b = (const float*)d_in[11];
    const float* gain_w = (const float*)d_in[12];
    const float* gain_b = (const float*)d_in[13];
    const float* kpre_w = (const float*)d_in[14];
    const float* kpre_b = (const float*)d_in[15];
    const float* vpost_w= (const float*)d_in[16];
    const float* vpost_b= (const float*)d_in[17];
    const float* kcand_w= (const float*)d_in[18];
    const float* kcand_b= (const float*)d_in[19];
    const float* vcand_w= (const float*)d_in[20];
    const float* vcand_b= (const float*)d_in[21];
    const float* nov_w  = (const float*)d_in[22];
    const float* nov_b  = (const float*)d_in[23];

    float* out = (float*)d_out;
    float* o_xout = out + OFF_XOUT;
    float* o_z    = out + OFF_Z;
    float* o_zhat = out + OFF_ZHAT;
    float* o_surp = out + OFF_SURP;
    float* o_kc   = out + OFF_KC;
    float* o_vc   = out + OFF_VC;
    float* o_gate = out + OFF_GATE;
    float* o_qn   = out + OFF_QN;
    float* o_vn   = out + OFF_VN;
    float* o_wn   = out + OFF_WN;

    float *dlt, *gan, *hh, *uu;
    cudaGetSymbolAddress((void**)&dlt, g_delta);
    cudaGetSymbolAddress((void**)&gan, g_gain);
    cudaGetSymbolAddress((void**)&hh,  g_h);
    cudaGetSymbolAddress((void**)&uu,  g_u);

    // 1) z = x @ enc + b ; delta = z - z_hat_prev
    gemm_k<0><<<dim3(64, 1, 16), 256>>>(x, enc_w, enc_b, o_z, zhp, dlt, 256, 64);
    // 2) surprise / gate
    surprise_k<<<8192, 256>>>(dlt, o_surp, o_gate);
    // 3) gain = 1 + 0.1*tanh(delta @ gain_w + b)
    gemm_k<2><<<dim3(64, 4, 16), 256>>>(dlt, gain_w, gain_b, gan, nullptr, nullptr, 64, 256);
    // 4) z_hat = z @ pred + b
    gemm_k<1><<<dim3(64, 1, 16), 256>>>(o_z, pred_w, pred_b, o_zhat, nullptr, nullptr, 64, 64);
    // 5) h = LN(x)*gain
    lngain_k<<<8192, 256>>>(x, ln_w, ln_b, gan, hh);
    // 6) u = gelu(h @ up + b)
    gemm_k<3><<<dim3(64, 16, 16), 256>>>(hh, up_w, up_b, uu, nullptr, nullptr, 256, 1024);
    // 7) x_out = x + u @ down + b
    gemm_k<4><<<dim3(64, 4, 16), 256>>>(uu, down_w, down_b, o_xout, x, nullptr, 1024, 256);
    // 8-11) heads
    gemm_k<1><<<dim3(64, 2, 16), 256>>>(o_xout, kpre_w,  kpre_b,  o_kc, nullptr, nullptr, 256, 128);
    gemm_k<1><<<dim3(64, 2, 16), 256>>>(o_xout, vpost_w, vpost_b, o_vc, nullptr, nullptr, 256, 128);
    gemm_k<1><<<dim3(64, 2, 16), 256>>>(o_xout, kcand_w, kcand_b, o_qn, nullptr, nullptr, 256, 128);
    gemm_k<1><<<dim3(64, 2, 16), 256>>>(o_xout, vcand_w, vcand_b, o_vn, nullptr, nullptr, 256, 128);
    // 12) unit-normalize k_cand and q_nov
    unitnorm_k<<<dim3(8192, 2), 256>>>(o_kc, o_qn);
    // 13) w_nov
    nov_k<<<8192, 256>>>(o_xout, nov_w, nov_b, o_wn);
}

// round 2
// speedup vs baseline: 2.4455x; 2.4455x over previous
#include <cuda_runtime.h>
#include <cuda_bf16.h>
#include <math.h>
#include <stdint.h>

// ---------------------------------------------------------------------------
// Dims: C=16, DCOL=256, DMEM=128, DPCM=64, EXP=4, BS=4, N=1024
// T = 4096 tokens, R = 65536 token-columns.
// Activations: [T, C, D] row-major. Weights: [C, Din, Dout].
// ---------------------------------------------------------------------------

#define TOK   4096
#define COLS  16
#define ROWS  (TOK * COLS)

// Output region offsets (floats)
#define OFF_XOUT   0UL
#define OFF_Z      16777216UL
#define OFF_ZHAT   20971520UL
#define OFF_SURP   25165824UL
#define OFF_KC     25231360UL
#define OFF_VC     33619968UL
#define OFF_GATE   42008576UL
#define OFF_QN     42074112UL
#define OFF_VN     50462720UL
#define OFF_WN     58851328UL

// Static device scratch
__device__ float g_delta[(size_t)ROWS * 64];
__device__ float g_gain [(size_t)ROWS * 256];
__device__ float g_h    [(size_t)ROWS * 256];
__device__ float g_u    [(size_t)ROWS * 1024];

__device__ __forceinline__ uint32_t f2tf(float x) {
    uint32_t u;
    asm("cvt.rna.tf32.f32 %0, %1;" : "=r"(u) : "f"(x));
    return u;
}

__device__ __forceinline__ void mma_tf32(float* d, const uint32_t* a, const uint32_t* b) {
    asm volatile(
        "mma.sync.aligned.m16n8k8.row.col.f32.tf32.tf32.f32 "
        "{%0,%1,%2,%3}, {%4,%5,%6,%7}, {%8,%9}, {%0,%1,%2,%3};"
        : "+f"(d[0]), "+f"(d[1]), "+f"(d[2]), "+f"(d[3])
        : "r"(a[0]), "r"(a[1]), "r"(a[2]), "r"(a[3]), "r"(b[0]), "r"(b[1]));
}

// ---------------------------------------------------------------------------
// tf32 tensor-core GEMM: Out[t,c,n] = epi( sum_k A[t,c,k] * W[c,k,n] + bias[c,n] )
// Block 128 x BN x 32, 256 threads (8 warps as 4Mx2N), warp tile 32 x BN/2.
// Double-buffered smem; A [m][k] pad 36; B [k][n] ld BN+8 (both LDS conflict-free).
// EPI: 0 = Out=v, auxo=v-aux | 1 = v | 2 = 1+0.1*tanh(v) | 3 = gelu | 4 = v+aux
// ---------------------------------------------------------------------------
template <int EPI, int BN>
__global__ __launch_bounds__(256)
void gemm_mma(const float* __restrict__ A, const float* __restrict__ W,
              const float* __restrict__ bias, float* __restrict__ Out,
              const float* __restrict__ aux, float* __restrict__ auxo,
              int K, int N)
{
    constexpr int BM = 128, BK = 32;
    constexpr int LDA = 36;            // floats per A smem row
    constexpr int LDB = BN + 8;        // floats per B smem row
    constexpr int ASZ = BM * LDA;
    constexpr int BSZ = BK * LDB;
    constexpr int NT  = BN / 16;       // n-tiles per warp (warp covers BN/2 cols, 8 each)
    constexpr int BTR = BN / 4;        // B loader: threads per row
    constexpr int BRP = 256 / BTR;     // B loader: rows per pass
    constexpr int BP  = BK / BRP;      // B loader: passes

    extern __shared__ uint32_t smem[];
    uint32_t* As = smem;               // [2][BM][LDA]
    uint32_t* Bs = smem + 2 * ASZ;     // [2][BK][LDB]

    const int c  = blockIdx.z;
    const int m0 = blockIdx.x * BM;
    const int n0 = blockIdx.y * BN;

    const int tid  = threadIdx.x;
    const int lane = tid & 31;
    const int warp = tid >> 5;
    const int wm = warp & 3;           // 0..3 -> 32-row band
    const int wn = warp >> 2;          // 0..1 -> BN/2-col band
    const int g  = lane >> 2;          // 0..7
    const int t  = lane & 3;           // 0..3

    // A loader: thread handles rows ar+32*i (i=0..3), k-offset akk..akk+3
    const int ar  = tid >> 3;
    const int akk = (tid & 7) * 4;
    const float* Ag = A + ((size_t)(m0 + ar) * COLS + c) * K + akk;
    const size_t AROW32 = (size_t)32 * COLS * K;   // 32 rows in global floats

    // B loader
    const int brow = tid / BTR;
    const int bn4  = (tid % BTR) * 4;
    const float* Bg = W + ((size_t)c * K + brow) * N + n0 + bn4;

    float4 pa[4];
    float4 pb[4];

    const int KT = K / BK;

    float acc[2][NT][4];
#pragma unroll
    for (int mi = 0; mi < 2; mi++)
#pragma unroll
        for (int ni = 0; ni < NT; ni++)
#pragma unroll
            for (int j = 0; j < 4; j++) acc[mi][ni][j] = 0.f;

    // ---- prologue: tile 0 -> regs -> smem buf 0
#pragma unroll
    for (int i = 0; i < 4; i++) pa[i] = *(const float4*)(Ag + (size_t)i * AROW32);
#pragma unroll
    for (int p = 0; p < BP; p++) pb[p] = *(const float4*)(Bg + (size_t)p * BRP * N);
#pragma unroll
    for (int i = 0; i < 4; i++) {
        uint4 u = { f2tf(pa[i].x), f2tf(pa[i].y), f2tf(pa[i].z), f2tf(pa[i].w) };
        *(uint4*)&As[(ar + 32 * i) * LDA + akk] = u;
    }
#pragma unroll
    for (int p = 0; p < BP; p++) {
        uint4 u = { f2tf(pb[p].x), f2tf(pb[p].y), f2tf(pb[p].z), f2tf(pb[p].w) };
        *(uint4*)&Bs[(brow + p * BRP) * LDB + bn4] = u;
    }

    int cur = 0;
    for (int kt = 0; kt < KT; kt++) {
        __syncthreads();
        const bool hasNext = (kt + 1 < KT);
        if (hasNext) {
            const size_t ko = (size_t)(kt + 1) * BK;
#pragma unroll
            for (int i = 0; i < 4; i++)
                pa[i] = *(const float4*)(Ag + (size_t)i * AROW32 + ko);
#pragma unroll
            for (int p = 0; p < BP; p++)
                pb[p] = *(const float4*)(Bg + (ko + (size_t)p * BRP) * N);
        }

        const uint32_t* Ab = &As[cur * ASZ];
        const uint32_t* Bb = &Bs[cur * BSZ];
#pragma unroll
        for (int ks = 0; ks < 4; ks++) {
            const int k0 = ks * 8;
            uint32_t af[2][4];
#pragma unroll
            for (int mi = 0; mi < 2; mi++) {
                const int mr = wm * 32 + mi * 16 + g;
                af[mi][0] = Ab[mr * LDA + k0 + t];
                af[mi][1] = Ab[(mr + 8) * LDA + k0 + t];
                af[mi][2] = Ab[mr * LDA + k0 + t + 4];
                af[mi][3] = Ab[(mr + 8) * LDA + k0 + t + 4];
            }
            uint32_t bf[NT][2];
#pragma unroll
            for (int ni = 0; ni < NT; ni++) {
                const int nc = wn * (BN / 2) + ni * 8 + g;
                bf[ni][0] = Bb[(k0 + t) * LDB + nc];
                bf[ni][1] = Bb[(k0 + t + 4) * LDB + nc];
            }
#pragma unroll
            for (int mi = 0; mi < 2; mi++)
#pragma unroll
                for (int ni = 0; ni < NT; ni++)
                    mma_tf32(acc[mi][ni], af[mi], bf[ni]);
        }

        if (hasNext) {
            const int nb = cur ^ 1;
#pragma unroll
            for (int i = 0; i < 4; i++) {
                uint4 u = { f2tf(pa[i].x), f2tf(pa[i].y), f2tf(pa[i].z), f2tf(pa[i].w) };
                *(uint4*)&As[nb * ASZ + (ar + 32 * i) * LDA + akk] = u;
            }
#pragma unroll
            for (int p = 0; p < BP; p++) {
                uint4 u = { f2tf(pb[p].x), f2tf(pb[p].y), f2tf(pb[p].z), f2tf(pb[p].w) };
                *(uint4*)&Bs[nb * BSZ + (brow + p * BRP) * LDB + bn4] = u;
            }
        }
        cur ^= 1;
    }

    // ---- epilogue
#pragma unroll
    for (int mi = 0; mi < 2; mi++) {
        const int r0 = m0 + wm * 32 + mi * 16 + g;   // rows r0 and r0+8
#pragma unroll
        for (int ni = 0; ni < NT; ni++) {
            const int n = n0 + wn * (BN / 2) + ni * 8 + 2 * t;
            const float b0 = bias[c * N + n];
            const float b1 = bias[c * N + n + 1];
#pragma unroll
            for (int half = 0; half < 2; half++) {
                const int r = r0 + half * 8;
                const size_t idx = ((size_t)r * COLS + c) * N + n;
                float v0 = acc[mi][ni][half * 2 + 0] + b0;
                float v1 = acc[mi][ni][half * 2 + 1] + b1;
                if (EPI == 0) {
                    float2 zp = *(const float2*)(aux + idx);
                    *(float2*)(Out + idx)  = make_float2(v0, v1);
                    *(float2*)(auxo + idx) = make_float2(v0 - zp.x, v1 - zp.y);
                } else if (EPI == 1) {
                    *(float2*)(Out + idx) = make_float2(v0, v1);
                } else if (EPI == 2) {
                    *(float2*)(Out + idx) = make_float2(1.0f + 0.1f * tanhf(v0),
                                                        1.0f + 0.1f * tanhf(v1));
                } else if (EPI == 3) {
                    *(float2*)(Out + idx) = make_float2(v0 * normcdff(v0),
                                                        v1 * normcdff(v1));
                } else {  // EPI == 4
                    float2 xv = *(const float2*)(aux + idx);
                    *(float2*)(Out + idx) = make_float2(v0 + xv.x, v1 + xv.y);
                }
            }
        }
    }
}

// ---------------------------------------------------------------------------
// Elementwise kernels (unchanged from Round 1)
// ---------------------------------------------------------------------------
__global__ __launch_bounds__(256)
void surprise_k(const float* __restrict__ delta,
                float* __restrict__ surp, float* __restrict__ gate)
{
    const int r = blockIdx.x * 8 + (threadIdx.x >> 5);
    const int lane = threadIdx.x & 31;
    const size_t base = (size_t)r * 64;
    float d0 = delta[base + lane];
    float d1 = delta[base + lane + 32];
    float s = d0 * d0 + d1 * d1;
#pragma unroll
    for (int o = 16; o > 0; o >>= 1) s += __shfl_xor_sync(0xFFFFFFFFu, s, o);
    if (lane == 0) {
        s *= (1.0f / 64.0f);
        surp[r] = s;
        gate[r] = fminf(s, 1.0f);
    }
}

__global__ __launch_bounds__(256)
void lngain_k(const float* __restrict__ x, const float* __restrict__ ln_w,
              const float* __restrict__ ln_b, const float* __restrict__ gain,
              float* __restrict__ h)
{
    const int r = blockIdx.x * 8 + (threadIdx.x >> 5);
    const int lane = threadIdx.x & 31;
    const int c = r & (COLS - 1);
    const size_t base = (size_t)r * 256;

    float v[8];
    float sum = 0.f, sq = 0.f;
#pragma unroll
    for (int i = 0; i < 8; i++) {
        v[i] = x[base + lane + 32 * i];
        sum += v[i];
        sq  += v[i] * v[i];
    }
#pragma unroll
    for (int o = 16; o > 0; o >>= 1) {
        sum += __shfl_xor_sync(0xFFFFFFFFu, sum, o);
        sq  += __shfl_xor_sync(0xFFFFFFFFu, sq, o);
    }
    const float m  = sum * (1.0f / 256.0f);
    const float var = sq * (1.0f / 256.0f) - m * m;
    const float rs = rsqrtf(var + 1e-5f);
#pragma unroll
    for (int i = 0; i < 8; i++) {
        const int d = lane + 32 * i;
        float hv = ((v[i] - m) * rs) * ln_w[c * 256 + d] + ln_b[c * 256 + d];
        h[base + d] = hv * gain[base + d];
    }
}

__global__ __launch_bounds__(256)
void unitnorm_k(float* __restrict__ p0, float* __restrict__ p1)
{
    float* p = (blockIdx.y == 0) ? p0 : p1;
    const int r = blockIdx.x * 8 + (threadIdx.x >> 5);
    const int lane = threadIdx.x & 31;
    const size_t base = (size_t)r * 128;
    float v[4];
    float s = 0.f;
#pragma unroll
    for (int i = 0; i < 4; i++) {
        v[i] = p[base + lane + 32 * i];
        s += v[i] * v[i];
    }
#pragma unroll
    for (int o = 16; o > 0; o >>= 1) s += __shfl_xor_sync(0xFFFFFFFFu, s, o);
    const float inv = 1.0f / fmaxf(sqrtf(s), 1e-12f);
#pragma unroll
    for (int i = 0; i < 4; i++) p[base + lane + 32 * i] = v[i] * inv;
}

__global__ __launch_bounds__(256)
void nov_k(const float* __restrict__ xout, const float* __restrict__ nov_w,
           const float* __restrict__ nov_b, float* __restrict__ wn)
{
    const int r = blockIdx.x * 8 + (threadIdx.x >> 5);
    const int lane = threadIdx.x & 31;
    const int c = r & (COLS - 1);
    const size_t base = (size_t)r * 256;
    float acc = 0.f;
#pragma unroll
    for (int i = 0; i < 8; i++) {
        const int d = lane + 32 * i;
        acc += xout[base + d] * nov_w[c * 256 + d];
    }
#pragma unroll
    for (int o = 16; o > 0; o >>= 1) acc += __shfl_xor_sync(0xFFFFFFFFu, acc, o);
    if (lane == 0) {
        const float z = acc + nov_b[c];
        wn[r] = 1.0f / (1.0f + expf(-z));
    }
}

// ---------------------------------------------------------------------------
// Launcher
// ---------------------------------------------------------------------------
static inline void set_smem(const void* f, int bytes) {
    cudaFuncSetAttribute(f, cudaFuncAttributeMaxDynamicSharedMemorySize, bytes);
}

extern "C" void kernel_launch(void* const* d_in, const int* in_sizes, int n_in,
                              void* d_out, int out_size)
{
    const float* x      = (const float*)d_in[0];
    const float* zhp    = (const float*)d_in[1];
    const float* ln_w   = (const float*)d_in[2];
    const float* ln_b   = (const float*)d_in[3];
    const float* up_w   = (const float*)d_in[4];
    const float* up_b   = (const float*)d_in[5];
    const float* down_w = (const float*)d_in[6];
    const float* down_b = (const float*)d_in[7];
    const float* enc_w  = (const float*)d_in[8];
    const float* enc_b  = (const float*)d_in[9];
    const float* pred_w = (const float*)d_in[10];
    const float* pred_b = (const float*)d_in[11];
    const float* gain_w = (const float*)d_in[12];
    const float* gain_b = (const float*)d_in[13];
    const float* kpre_w = (const float*)d_in[14];
    const float* kpre_b = (const float*)d_in[15];
    const float* vpost_w= (const float*)d_in[16];
    const float* vpost_b= (const float*)d_in[17];
    const float* kcand_w= (const float*)d_in[18];
    const float* kcand_b= (const float*)d_in[19];
    const float* vcand_w= (const float*)d_in[20];
    const float* vcand_b= (const float*)d_in[21];
    const float* nov_w  = (const float*)d_in[22];
    const float* nov_b  = (const float*)d_in[23];

    float* out = (float*)d_out;
    float* o_xout = out + OFF_XOUT;
    float* o_z    = out + OFF_Z;
    float* o_zhat = out + OFF_ZHAT;
    float* o_surp = out + OFF_SURP;
    float* o_kc   = out + OFF_KC;
    float* o_vc   = out + OFF_VC;
    float* o_gate = out + OFF_GATE;
    float* o_qn   = out + OFF_QN;
    float* o_vn   = out + OFF_VN;
    float* o_wn   = out + OFF_WN;

    float *dlt, *gan, *hh, *uu;
    cudaGetSymbolAddress((void**)&dlt, g_delta);
    cudaGetSymbolAddress((void**)&gan, g_gain);
    cudaGetSymbolAddress((void**)&hh,  g_h);
    cudaGetSymbolAddress((void**)&uu,  g_u);

    // smem sizes: BN=128 -> 71680 B, BN=64 -> 55296 B
    const int SM128 = (2 * 128 * 36 + 2 * 32 * 136) * 4;
    const int SM64  = (2 * 128 * 36 + 2 * 32 * 72) * 4;
    set_smem((const void*)gemm_mma<0, 64>,  SM64);
    set_smem((const void*)gemm_mma<1, 64>,  SM64);
    set_smem((const void*)gemm_mma<2, 128>, SM128);
    set_smem((const void*)gemm_mma<3, 128>, SM128);
    set_smem((const void*)gemm_mma<4, 128>, SM128);
    set_smem((const void*)gemm_mma<1, 128>, SM128);

    // 1) z = x @ enc + b ; delta = z - z_hat_prev
    gemm_mma<0, 64><<<dim3(32, 1, 16), 256, SM64>>>(x, enc_w, enc_b, o_z, zhp, dlt, 256, 64);
    // 2) surprise / gate
    surprise_k<<<8192, 256>>>(dlt, o_surp, o_gate);
    // 3) gain = 1 + 0.1*tanh(delta @ gain_w + b)
    gemm_mma<2, 128><<<dim3(32, 2, 16), 256, SM128>>>(dlt, gain_w, gain_b, gan, nullptr, nullptr, 64, 256);
    // 4) z_hat = z @ pred + b
    gemm_mma<1, 64><<<dim3(32, 1, 16), 256, SM64>>>(o_z, pred_w, pred_b, o_zhat, nullptr, nullptr, 64, 64);
    // 5) h = LN(x)*gain
    lngain_k<<<8192, 256>>>(x, ln_w, ln_b, gan, hh);
    // 6) u = gelu(h @ up + b)
    gemm_mma<3, 128><<<dim3(32, 8, 16), 256, SM128>>>(hh, up_w, up_b, uu, nullptr, nullptr, 256, 1024);
    // 7) x_out = x + u @ down + b
    gemm_mma<4, 128><<<dim3(32, 2, 16), 256, SM128>>>(uu, down_w, down_b, o_xout, x, nullptr, 1024, 256);
    // 8-11) heads
    gemm_mma<1, 128><<<dim3(32, 1, 16), 256, SM128>>>(o_xout, kpre_w,  kpre_b,  o_kc, nullptr, nullptr, 256, 128);
    gemm_mma<1, 128><<<dim3(32, 1, 16), 256, SM128>>>(o_xout, vpost_w, vpost_b, o_vc, nullptr, nullptr, 256, 128);
    gemm_mma<1, 128><<<dim3(32, 1, 16), 256, SM128>>>(o_xout, kcand_w, kcand_b, o_qn, nullptr, nullptr, 256, 128);
    gemm_mma<1, 128><<<dim3(32, 1, 16), 256, SM128>>>(o_xout, vcand_w, vcand_b, o_vn, nullptr, nullptr, 256, 128);
    // 12) unit-normalize k_cand and q_nov
    unitnorm_k<<<dim3(8192, 2), 256>>>(o_kc, o_qn);
    // 13) w_nov
    nov_k<<<8192, 256>>>(o_wn ? o_xout : o_xout, nov_w, nov_b, o_wn);
}

// round 3
// speedup vs baseline: 2.9089x; 1.1895x over previous
#include <cuda_runtime.h>
#include <cuda_bf16.h>
#include <math.h>
#include <stdint.h>

// ---------------------------------------------------------------------------
// Dims: C=16, DCOL=256, DMEM=128, DPCM=64, EXP=4, BS=4, N=1024
// T = 4096 tokens, R = 65536 token-columns.
// Activations: [T, C, D] row-major. Weights: [C, Din, Dout].
// ---------------------------------------------------------------------------

#define TOK   4096
#define COLS  16
#define ROWS  (TOK * COLS)

#define OFF_XOUT   0UL
#define OFF_Z      16777216UL
#define OFF_ZHAT   20971520UL
#define OFF_SURP   25165824UL
#define OFF_KC     25231360UL
#define OFF_VC     33619968UL
#define OFF_GATE   42008576UL
#define OFF_QN     42074112UL
#define OFF_VN     50462720UL
#define OFF_WN     58851328UL

__device__ float g_delta[(size_t)ROWS * 64];
__device__ float g_gain [(size_t)ROWS * 256];
__device__ float g_h    [(size_t)ROWS * 256];
__device__ float g_u    [(size_t)ROWS * 1024];

__device__ __forceinline__ uint32_t f2tf(float x) {
    uint32_t u;
    asm("cvt.rna.tf32.f32 %0, %1;" : "=r"(u) : "f"(x));
    return u;
}

__device__ __forceinline__ void mma_tf32(float* d, const uint32_t* a, const uint32_t* b) {
    asm volatile(
        "mma.sync.aligned.m16n8k8.row.col.f32.tf32.tf32.f32 "
        "{%0,%1,%2,%3}, {%4,%5,%6,%7}, {%8,%9}, {%0,%1,%2,%3};"
        : "+f"(d[0]), "+f"(d[1]), "+f"(d[2]), "+f"(d[3])
        : "r"(a[0]), "r"(a[1]), "r"(a[2]), "r"(a[3]), "r"(b[0]), "r"(b[1]));
}

__device__ __forceinline__ void cp16(uint32_t saddr, const void* gaddr) {
    asm volatile("cp.async.cg.shared.global [%0], [%1], 16;" :: "r"(saddr), "l"(gaddr));
}
__device__ __forceinline__ void cp_commit() {
    asm volatile("cp.async.commit_group;");
}
__device__ __forceinline__ void cp_wait2() {
    asm volatile("cp.async.wait_group 2;");
}

// ---------------------------------------------------------------------------
// tf32 MMA GEMM with 4-stage cp.async pipeline.
// Block 128 x BN x K, BK=16 per stage. 8 warps (4M x 2N), warp tile 32 x BN/2.
// A smem: [row][16] raw fp32, XOR-swizzled (chunk ^= (row>>1)&3) -> conflict-free
//         for both 16B async stores and 32b fragment loads.
// B smem: [k][BN] raw fp32, ld = BN+8 (conflict-free both directions).
// tf32 conversion happens at fragment-load time (cvt.rna).
// EPI: 0 = Out=v, auxo=v-aux | 1 = v | 2 = 1+0.1*tanh(v) | 3 = gelu | 4 = v+aux
// ---------------------------------------------------------------------------
template <int EPI, int BN>
__global__ __launch_bounds__(256)
void gemm_mma(const float* __restrict__ A, const float* __restrict__ W,
              const float* __restrict__ bias, float* __restrict__ Out,
              const float* __restrict__ aux, float* __restrict__ auxo,
              int K, int N)
{
    constexpr int BM = 128, BK = 16, S = 4;
    constexpr int ASTG = BM * BK;            // floats per A stage (2048)
    constexpr int LDB  = BN + 8;
    constexpr int BSTG = BK * LDB;           // floats per B stage
    constexpr int NT   = BN / 16;            // n-tiles per warp
    constexpr int BTR  = BN / 4;             // B loader threads per row
    constexpr int BRP  = 256 / BTR;          // B loader rows per pass
    constexpr int BP   = BK / BRP;           // B loader passes

    extern __shared__ float smem[];
    float* As = smem;                        // [S][ASTG]
    float* Bs = smem + S * ASTG;             // [S][BSTG]

    uint32_t smem_u32;
    {
        asm("{ .reg .u64 t; cvta.to.shared.u64 t, %1; cvt.u32.u64 %0, t; }"
            : "=r"(smem_u32) : "l"(smem));
    }
    const uint32_t As_u = smem_u32;
    const uint32_t Bs_u = smem_u32 + S * ASTG * 4;

    const int c  = blockIdx.z;
    const int m0 = blockIdx.x * BM;
    const int n0 = blockIdx.y * BN;

    const int tid  = threadIdx.x;
    const int lane = tid & 31;
    const int warp = tid >> 5;
    const int wm = warp & 3;
    const int wn = warp >> 2;
    const int g  = lane >> 2;
    const int t  = lane & 3;

    // --- A loader: 4 threads/row, 64 rows/pass, 2 passes
    const int rowA = tid >> 2;
    const int chA  = tid & 3;                     // 16B chunk index (k-chunk)
    const int swA  = (rowA >> 1) & 3;             // same for rowA and rowA+64
    const uint32_t sA_off = (uint32_t)(rowA * BK + ((chA ^ swA) << 2)) * 4;
    const float* Ag = A + ((size_t)(m0 + rowA) * COLS + c) * K + chA * 4;
    const size_t AGP = (size_t)64 * COLS * K;     // pass stride (64 rows)

    // --- B loader
    const int rowB = tid / BTR;
    const int nB   = (tid % BTR) * 4;
    const float* Bg = W + ((size_t)c * K + rowB) * N + n0 + nB;
    const uint32_t sB_off = (uint32_t)(rowB * LDB + nB) * 4;

    const int KT = K / BK;

    float acc[2][NT][4];
#pragma unroll
    for (int mi = 0; mi < 2; mi++)
#pragma unroll
        for (int ni = 0; ni < NT; ni++)
#pragma unroll
            for (int j = 0; j < 4; j++) acc[mi][ni][j] = 0.f;

    // issue one stage of loads
    auto issue = [&](int kt, int slot) {
        const uint32_t sa = As_u + (uint32_t)slot * ASTG * 4 + sA_off;
        const float*   ga = Ag + (size_t)kt * BK;
        cp16(sa,                    ga);
        cp16(sa + 64 * BK * 4,      ga + AGP);
        const uint32_t sb = Bs_u + (uint32_t)slot * BSTG * 4 + sB_off;
        const float*   gb = Bg + (size_t)kt * BK * N;
#pragma unroll
        for (int p = 0; p < BP; p++)
            cp16(sb + (uint32_t)(p * BRP * LDB) * 4, gb + (size_t)p * BRP * N);
    };

    // prologue: stages 0..2 (KT >= 4 always)
    issue(0, 0); cp_commit();
    issue(1, 1); cp_commit();
    issue(2, 2); cp_commit();

    for (int kt = 0; kt < KT; kt++) {
        cp_wait2();
        __syncthreads();
        const int pf = kt + 3;
        if (pf < KT) issue(pf, pf & 3);
        cp_commit();

        const float* Ab = As + (kt & 3) * ASTG;
        const float* Bb = Bs + (kt & 3) * BSTG;

#pragma unroll
        for (int ks = 0; ks < 2; ks++) {
            const int k0 = ks * 8;
            const int c0 = k0 >> 2;                 // 0 or 2
            uint32_t af[2][4];
#pragma unroll
            for (int mi = 0; mi < 2; mi++) {
                const int mr = wm * 32 + mi * 16 + g;
                const int sw = (mr >> 1) & 3;
                const int o1 = mr * BK + ((c0 ^ sw) << 2) + t;
                const int o2 = mr * BK + (((c0 + 1) ^ sw) << 2) + t;
                af[mi][0] = f2tf(Ab[o1]);
                af[mi][1] = f2tf(Ab[o1 + 8 * BK]);
                af[mi][2] = f2tf(Ab[o2]);
                af[mi][3] = f2tf(Ab[o2 + 8 * BK]);
            }
            uint32_t bf[NT][2];
#pragma unroll
            for (int ni = 0; ni < NT; ni++) {
                const int nc = wn * (BN / 2) + ni * 8 + g;
                bf[ni][0] = f2tf(Bb[(k0 + t) * LDB + nc]);
                bf[ni][1] = f2tf(Bb[(k0 + t + 4) * LDB + nc]);
            }
#pragma unroll
            for (int mi = 0; mi < 2; mi++)
#pragma unroll
                for (int ni = 0; ni < NT; ni++)
                    mma_tf32(acc[mi][ni], af[mi], bf[ni]);
        }
    }

    // ---- epilogue
#pragma unroll
    for (int mi = 0; mi < 2; mi++) {
        const int r0 = m0 + wm * 32 + mi * 16 + g;
#pragma unroll
        for (int ni = 0; ni < NT; ni++) {
            const int n = n0 + wn * (BN / 2) + ni * 8 + 2 * t;
            const float b0 = bias[c * N + n];
            const float b1 = bias[c * N + n + 1];
#pragma unroll
            for (int half = 0; half < 2; half++) {
                const int r = r0 + half * 8;
                const size_t idx = ((size_t)r * COLS + c) * N + n;
                float v0 = acc[mi][ni][half * 2 + 0] + b0;
                float v1 = acc[mi][ni][half * 2 + 1] + b1;
                if (EPI == 0) {
                    float2 zp = *(const float2*)(aux + idx);
                    *(float2*)(Out + idx)  = make_float2(v0, v1);
                    *(float2*)(auxo + idx) = make_float2(v0 - zp.x, v1 - zp.y);
                } else if (EPI == 1) {
                    *(float2*)(Out + idx) = make_float2(v0, v1);
                } else if (EPI == 2) {
                    *(float2*)(Out + idx) = make_float2(1.0f + 0.1f * tanhf(v0),
                                                        1.0f + 0.1f * tanhf(v1));
                } else if (EPI == 3) {
                    *(float2*)(Out + idx) = make_float2(v0 * normcdff(v0),
                                                        v1 * normcdff(v1));
                } else {
                    float2 xv = *(const float2*)(aux + idx);
                    *(float2*)(Out + idx) = make_float2(v0 + xv.x, v1 + xv.y);
                }
            }
        }
    }
}

// ---------------------------------------------------------------------------
// Elementwise kernels
// ---------------------------------------------------------------------------
__global__ __launch_bounds__(256)
void surprise_k(const float* __restrict__ delta,
                float* __restrict__ surp, float* __restrict__ gate)
{
    const int r = blockIdx.x * 8 + (threadIdx.x >> 5);
    const int lane = threadIdx.x & 31;
    const size_t base = (size_t)r * 64;
    float d0 = delta[base + lane];
    float d1 = delta[base + lane + 32];
    float s = d0 * d0 + d1 * d1;
#pragma unroll
    for (int o = 16; o > 0; o >>= 1) s += __shfl_xor_sync(0xFFFFFFFFu, s, o);
    if (lane == 0) {
        s *= (1.0f / 64.0f);
        surp[r] = s;
        gate[r] = fminf(s, 1.0f);
    }
}

__global__ __launch_bounds__(256)
void lngain_k(const float* __restrict__ x, const float* __restrict__ ln_w,
              const float* __restrict__ ln_b, const float* __restrict__ gain,
              float* __restrict__ h)
{
    const int r = blockIdx.x * 8 + (threadIdx.x >> 5);
    const int lane = threadIdx.x & 31;
    const int c = r & (COLS - 1);
    const size_t base = (size_t)r * 256;

    float v[8];
    float sum = 0.f, sq = 0.f;
#pragma unroll
    for (int i = 0; i < 8; i++) {
        v[i] = x[base + lane + 32 * i];
        sum += v[i];
        sq  += v[i] * v[i];
    }
#pragma unroll
    for (int o = 16; o > 0; o >>= 1) {
        sum += __shfl_xor_sync(0xFFFFFFFFu, sum, o);
        sq  += __shfl_xor_sync(0xFFFFFFFFu, sq, o);
    }
    const float m  = sum * (1.0f / 256.0f);
    const float var = sq * (1.0f / 256.0f) - m * m;
    const float rs = rsqrtf(var + 1e-5f);
#pragma unroll
    for (int i = 0; i < 8; i++) {
        const int d = lane + 32 * i;
        float hv = ((v[i] - m) * rs) * ln_w[c * 256 + d] + ln_b[c * 256 + d];
        h[base + d] = hv * gain[base + d];
    }
}

__global__ __launch_bounds__(256)
void unitnorm_k(float* __restrict__ p0, float* __restrict__ p1)
{
    float* p = (blockIdx.y == 0) ? p0 : p1;
    const int r = blockIdx.x * 8 + (threadIdx.x >> 5);
    const int lane = threadIdx.x & 31;
    const size_t base = (size_t)r * 128;
    float v[4];
    float s = 0.f;
#pragma unroll
    for (int i = 0; i < 4; i++) {
        v[i] = p[base + lane + 32 * i];
        s += v[i] * v[i];
    }
#pragma unroll
    for (int o = 16; o > 0; o >>= 1) s += __shfl_xor_sync(0xFFFFFFFFu, s, o);
    const float inv = 1.0f / fmaxf(sqrtf(s), 1e-12f);
#pragma unroll
    for (int i = 0; i < 4; i++) p[base + lane + 32 * i] = v[i] * inv;
}

__global__ __launch_bounds__(256)
void nov_k(const float* __restrict__ xout, const float* __restrict__ nov_w,
           const float* __restrict__ nov_b, float* __restrict__ wn)
{
    const int r = blockIdx.x * 8 + (threadIdx.x >> 5);
    const int lane = threadIdx.x & 31;
    const int c = r & (COLS - 1);
    const size_t base = (size_t)r * 256;
    float acc = 0.f;
#pragma unroll
    for (int i = 0; i < 8; i++) {
        const int d = lane + 32 * i;
        acc += xout[base + d] * nov_w[c * 256 + d];
    }
#pragma unroll
    for (int o = 16; o > 0; o >>= 1) acc += __shfl_xor_sync(0xFFFFFFFFu, acc, o);
    if (lane == 0) {
        const float z = acc + nov_b[c];
        wn[r] = 1.0f / (1.0f + expf(-z));
    }
}

// ---------------------------------------------------------------------------
// Launcher
// ---------------------------------------------------------------------------
static inline void set_smem(const void* f, int bytes) {
    cudaFuncSetAttribute(f, cudaFuncAttributeMaxDynamicSharedMemorySize, bytes);
}

extern "C" void kernel_launch(void* const* d_in, const int* in_sizes, int n_in,
                              void* d_out, int out_size)
{
    const float* x      = (const float*)d_in[0];
    const float* zhp    = (const float*)d_in[1];
    const float* ln_w   = (const float*)d_in[2];
    const float* ln_b   = (const float*)d_in[3];
    const float* up_w   = (const float*)d_in[4];
    const float* up_b   = (const float*)d_in[5];
    const float* down_w = (const float*)d_in[6];
    const float* down_b = (const float*)d_in[7];
    const float* enc_w  = (const float*)d_in[8];
    const float* enc_b  = (const float*)d_in[9];
    const float* pred_w = (const float*)d_in[10];
    const float* pred_b = (const float*)d_in[11];
    const float* gain_w = (const float*)d_in[12];
    const float* gain_b = (const float*)d_in[13];
    const float* kpre_w = (const float*)d_in[14];
    const float* kpre_b = (const float*)d_in[15];
    const float* vpost_w= (const float*)d_in[16];
    const float* vpost_b= (const float*)d_in[17];
    const float* kcand_w= (const float*)d_in[18];
    const float* kcand_b= (const float*)d_in[19];
    const float* vcand_w= (const float*)d_in[20];
    const float* vcand_b= (const float*)d_in[21];
    const float* nov_w  = (const float*)d_in[22];
    const float* nov_b  = (const float*)d_in[23];

    float* out = (float*)d_out;
    float* o_xout = out + OFF_XOUT;
    float* o_z    = out + OFF_Z;
    float* o_zhat = out + OFF_ZHAT;
    float* o_surp = out + OFF_SURP;
    float* o_kc   = out + OFF_KC;
    float* o_vc   = out + OFF_VC;
    float* o_gate = out + OFF_GATE;
    float* o_qn   = out + OFF_QN;
    float* o_vn   = out + OFF_VN;
    float* o_wn   = out + OFF_WN;

    float *dlt, *gan, *hh, *uu;
    cudaGetSymbolAddress((void**)&dlt, g_delta);
    cudaGetSymbolAddress((void**)&gan, g_gain);
    cudaGetSymbolAddress((void**)&hh,  g_h);
    cudaGetSymbolAddress((void**)&uu,  g_u);

    // smem: 4 stages: A 4*2048 floats + B 4*16*(BN+8) floats
    const int SM128 = (4 * 2048 + 4 * 16 * 136) * 4;   // 67584 B
    const int SM64  = (4 * 2048 + 4 * 16 * 72) * 4;    // 51200 B
    set_smem((const void*)gemm_mma<0, 64>,  SM64);
    set_smem((const void*)gemm_mma<1, 64>,  SM64);
    set_smem((const void*)gemm_mma<2, 128>, SM128);
    set_smem((const void*)gemm_mma<3, 128>, SM128);
    set_smem((const void*)gemm_mma<4, 128>, SM128);
    set_smem((const void*)gemm_mma<1, 128>, SM128);

    // 1) z = x @ enc + b ; delta = z - z_hat_prev
    gemm_mma<0, 64><<<dim3(32, 1, 16), 256, SM64>>>(x, enc_w, enc_b, o_z, zhp, dlt, 256, 64);
    // 2) surprise / gate
    surprise_k<<<8192, 256>>>(dlt, o_surp, o_gate);
    // 3) gain = 1 + 0.1*tanh(delta @ gain_w + b)
    gemm_mma<2, 128><<<dim3(32, 2, 16), 256, SM128>>>(dlt, gain_w, gain_b, gan, nullptr, nullptr, 64, 256);
    // 4) z_hat = z @ pred + b
    gemm_mma<1, 64><<<dim3(32, 1, 16), 256, SM64>>>(o_z, pred_w, pred_b, o_zhat, nullptr, nullptr, 64, 64);
    // 5) h = LN(x)*gain
    lngain_k<<<8192, 256>>>(x, ln_w, ln_b, gan, hh);
    // 6) u = gelu(h @ up + b)
    gemm_mma<3, 128><<<dim3(32, 8, 16), 256, SM128>>>(hh, up_w, up_b, uu, nullptr, nullptr, 256, 1024);
    // 7) x_out = x + u @ down + b
    gemm_mma<4, 128><<<dim3(32, 2, 16), 256, SM128>>>(uu, down_w, down_b, o_xout, x, nullptr, 1024, 256);
    // 8-11) heads
    gemm_mma<1, 128><<<dim3(32, 1, 16), 256, SM128>>>(o_xout, kpre_w,  kpre_b,  o_kc, nullptr, nullptr, 256, 128);
    gemm_mma<1, 128><<<dim3(32, 1, 16), 256, SM128>>>(o_xout, vpost_w, vpost_b, o_vc, nullptr, nullptr, 256, 128);
    gemm_mma<1, 128><<<dim3(32, 1, 16), 256, SM128>>>(o_xout, kcand_w, kcand_b, o_qn, nullptr, nullptr, 256, 128);
    gemm_mma<1, 128><<<dim3(32, 1, 16), 256, SM128>>>(o_xout, vcand_w, vcand_b, o_vn, nullptr, nullptr, 256, 128);
    // 12) unit-normalize k_cand and q_nov
    unitnorm_k<<<dim3(8192, 2), 256>>>(o_kc, o_qn);
    // 13) w_nov
    nov_k<<<8192, 256>>>(o_xout, nov_w, nov_b, o_wn);
}